// round 2
// baseline (speedup 1.0000x reference)
#include <cuda_runtime.h>
#include <cuda_bf16.h>
#include <math.h>

// Problem constants
#define BB 512
#define NN 200
#define DD 128
#define MTOK (BB * NN)        // 102400 tokens

// ---------------- scratch (static device globals; no allocation) ----------------
__device__ float g_hidden[MTOK * DD];          // (102400, 128)
__device__ float g_h2    [MTOK * 2 * DD];      // (102400, 256)  [h_in | h_out]
__device__ float g_inputs[MTOK * 2 * DD];      // (102400, 256)  [input_in | input_out]
__device__ float g_gi    [MTOK * 3 * DD];      // (102400, 384)
__device__ float g_gh    [MTOK * 3 * DD];      // (102400, 384)
__device__ float g_w2    [2 * DD * DD];        // (256, 128)  [w_in ; w_out]
__device__ float g_bias2 [2 * DD];             // (256)       [b_in ; b_out]

// ---------------- pack w_in/w_out into one weight ----------------
__global__ void pack_w2_kernel(const float* __restrict__ w_in,
                               const float* __restrict__ b_in,
                               const float* __restrict__ w_out,
                               const float* __restrict__ b_out,
                               float* __restrict__ w2,
                               float* __restrict__ bias2)
{
    int i = blockIdx.x * blockDim.x + threadIdx.x;
    if (i < DD * DD) {
        w2[i] = w_in[i];
        w2[DD * DD + i] = w_out[i];
    }
    if (i < DD) {
        bias2[i] = b_in[i];
        bias2[DD + i] = b_out[i];
    }
}

// ---------------- gather: hidden = emb[x] ----------------
__global__ void gather_kernel(const int* __restrict__ x,
                              const float* __restrict__ emb,
                              float* __restrict__ hidden)
{
    int idx = blockIdx.x * blockDim.x + threadIdx.x;   // over MTOK * 32 float4
    if (idx >= MTOK * (DD / 4)) return;
    int m  = idx >> 5;            // token
    int k4 = idx & 31;            // float4 within row
    int t  = x[m];
    reinterpret_cast<float4*>(hidden)[idx] =
        reinterpret_cast<const float4*>(emb + (size_t)t * DD)[k4];
}

// ---------------- generic TN GEMM (double-buffered, 1 sync/iter) ----------------
// C[m, n] = A[m,:K] . Bw[n,:K] + bias[n]
// A: row-major (M, lda); Bw: row-major (Ncols, K); C: row-major, ldc.
// Requires: M % 64 == 0, Ncols % 64 == 0, K % 32 == 0.
#define BM 64
#define BN 64
#define BKK 32
#define SPAD 68

__global__ void __launch_bounds__(256) gemm_tn_bias(
    const float* __restrict__ A, int lda,
    const float* __restrict__ Bw,
    const float* __restrict__ bias,
    float* __restrict__ C, int ldc, int K)
{
    __shared__ float As[2][BKK][SPAD];
    __shared__ float Bs[2][BKK][SPAD];

    const int tid = threadIdx.x;
    const size_t m0 = (size_t)blockIdx.x * BM;
    const int    n0 = blockIdx.y * BN;

    float acc[4][4] = {};

    const int tr = (tid >> 4) << 2;   // 0..60
    const int tc = (tid & 15) << 2;   // 0..60

    // load indices: each thread handles 2 rows of each tile (512 row-slots / 256 thr)
    const int l0row = tid >> 3;            // 0..31
    const int l0kk  = (tid & 7) << 2;      // 0..28

    const int ntiles = K / BKK;

    // ---- prologue: tile 0 -> buf 0 ----
    {
        #pragma unroll
        for (int h = 0; h < 2; h++) {
            int row = l0row + h * 32;
            float4 va = *reinterpret_cast<const float4*>(A + (m0 + row) * (size_t)lda + l0kk);
            As[0][l0kk + 0][row] = va.x; As[0][l0kk + 1][row] = va.y;
            As[0][l0kk + 2][row] = va.z; As[0][l0kk + 3][row] = va.w;
            float4 vb = *reinterpret_cast<const float4*>(Bw + (size_t)(n0 + row) * K + l0kk);
            Bs[0][l0kk + 0][row] = vb.x; Bs[0][l0kk + 1][row] = vb.y;
            Bs[0][l0kk + 2][row] = vb.z; Bs[0][l0kk + 3][row] = vb.w;
        }
    }
    __syncthreads();

    for (int t = 0; t < ntiles; t++) {
        const int cur = t & 1;
        const int nxt = cur ^ 1;

        // prefetch next tile into the other buffer (overlaps with compute below)
        if (t + 1 < ntiles) {
            int k0 = (t + 1) * BKK;
            #pragma unroll
            for (int h = 0; h < 2; h++) {
                int row = l0row + h * 32;
                float4 va = *reinterpret_cast<const float4*>(A + (m0 + row) * (size_t)lda + k0 + l0kk);
                As[nxt][l0kk + 0][row] = va.x; As[nxt][l0kk + 1][row] = va.y;
                As[nxt][l0kk + 2][row] = va.z; As[nxt][l0kk + 3][row] = va.w;
                float4 vb = *reinterpret_cast<const float4*>(Bw + (size_t)(n0 + row) * K + k0 + l0kk);
                Bs[nxt][l0kk + 0][row] = vb.x; Bs[nxt][l0kk + 1][row] = vb.y;
                Bs[nxt][l0kk + 2][row] = vb.z; Bs[nxt][l0kk + 3][row] = vb.w;
            }
        }

        #pragma unroll
        for (int k = 0; k < BKK; k++) {
            float a0 = As[cur][k][tr + 0], a1 = As[cur][k][tr + 1],
                  a2 = As[cur][k][tr + 2], a3 = As[cur][k][tr + 3];
            float b0 = Bs[cur][k][tc + 0], b1 = Bs[cur][k][tc + 1],
                  b2 = Bs[cur][k][tc + 2], b3 = Bs[cur][k][tc + 3];
            acc[0][0] += a0 * b0; acc[0][1] += a0 * b1; acc[0][2] += a0 * b2; acc[0][3] += a0 * b3;
            acc[1][0] += a1 * b0; acc[1][1] += a1 * b1; acc[1][2] += a1 * b2; acc[1][3] += a1 * b3;
            acc[2][0] += a2 * b0; acc[2][1] += a2 * b1; acc[2][2] += a2 * b2; acc[2][3] += a2 * b3;
            acc[3][0] += a3 * b0; acc[3][1] += a3 * b1; acc[3][2] += a3 * b2; acc[3][3] += a3 * b3;
        }
        __syncthreads();
    }

    #pragma unroll
    for (int j = 0; j < 4; j++) {
        float bj = bias[n0 + tc + j];
        #pragma unroll
        for (int i = 0; i < 4; i++) {
            C[(m0 + tr + i) * (size_t)ldc + n0 + tc + j] = acc[i][j] + bj;
        }
    }
}

// ---------------- batched NN GEMM (double-buffered) ----------------
// inputs[b,:,half*128:+128] = A[b][:, half*200:+200] @ h2[b,:,half*128:+128] + bias
// M=200, N=128, K=200 per (batch, half). grid = (4, 2, 1024), z = b*2 + half.
__global__ void __launch_bounds__(256) gemm_batched_adj(
    const float* __restrict__ Aten,    // (512, 200, 400)
    const float* __restrict__ h2,      // (102400, 256)
    const float* __restrict__ b_iah,
    const float* __restrict__ b_oah,
    float* __restrict__ inputs)        // (102400, 256)
{
    const int half = blockIdx.z & 1;
    const int b    = blockIdx.z >> 1;
    const int m0   = blockIdx.x * BM;     // 0,64,128,192
    const int n0   = blockIdx.y * BN;     // 0,64

    const float* Ab   = Aten + (size_t)b * NN * (2 * NN) + half * NN;
    const float* Hb   = h2   + (size_t)b * NN * 256 + half * 128;
    const float* bias = half ? b_oah : b_iah;

    __shared__ float As[2][BKK][SPAD];
    __shared__ float Bs[2][BKK][SPAD];

    const int tid = threadIdx.x;
    float acc[4][4] = {};

    const int tr = (tid >> 4) << 2;
    const int tc = (tid & 15) << 2;

    // A-tile load index (transpose into As[k][row])
    const int arow = tid >> 3;           // 0..31 (+32 second half)
    const int akk  = (tid & 7) << 2;     // 0..28
    // B-tile load index (direct into Bs[k][j])
    const int bkr  = tid >> 4;           // 0..15 (+16 second half)
    const int bjj  = (tid & 15) << 2;    // 0..60

    const int ntiles = (NN + BKK - 1) / BKK;   // 7

    // ---- prologue: tile 0 ----
    {
        #pragma unroll
        for (int h = 0; h < 2; h++) {
            int row = arow + h * 32;
            float4 va = make_float4(0.f, 0.f, 0.f, 0.f);
            if ((m0 + row) < NN && akk < NN)
                va = *reinterpret_cast<const float4*>(Ab + (size_t)(m0 + row) * (2 * NN) + akk);
            As[0][akk + 0][row] = va.x; As[0][akk + 1][row] = va.y;
            As[0][akk + 2][row] = va.z; As[0][akk + 3][row] = va.w;
        }
        #pragma unroll
        for (int h = 0; h < 2; h++) {
            int kr = bkr + h * 16;
            float4 vb = make_float4(0.f, 0.f, 0.f, 0.f);
            if (kr < NN)
                vb = *reinterpret_cast<const float4*>(Hb + (size_t)kr * 256 + n0 + bjj);
            *reinterpret_cast<float4*>(&Bs[0][kr][bjj]) = vb;
        }
    }
    __syncthreads();

    for (int t = 0; t < ntiles; t++) {
        const int cur = t & 1;
        const int nxt = cur ^ 1;

        if (t + 1 < ntiles) {
            int k0 = (t + 1) * BKK;
            #pragma unroll
            for (int h = 0; h < 2; h++) {
                int row = arow + h * 32;
                float4 va = make_float4(0.f, 0.f, 0.f, 0.f);
                if ((m0 + row) < NN && (k0 + akk) < NN)
                    va = *reinterpret_cast<const float4*>(Ab + (size_t)(m0 + row) * (2 * NN) + k0 + akk);
                As[nxt][akk + 0][row] = va.x; As[nxt][akk + 1][row] = va.y;
                As[nxt][akk + 2][row] = va.z; As[nxt][akk + 3][row] = va.w;
            }
            #pragma unroll
            for (int h = 0; h < 2; h++) {
                int kr = bkr + h * 16;
                float4 vb = make_float4(0.f, 0.f, 0.f, 0.f);
                if ((k0 + kr) < NN)
                    vb = *reinterpret_cast<const float4*>(Hb + (size_t)(k0 + kr) * 256 + n0 + bjj);
                *reinterpret_cast<float4*>(&Bs[nxt][kr][bjj]) = vb;
            }
        }

        #pragma unroll
        for (int k = 0; k < BKK; k++) {
            float a0 = As[cur][k][tr + 0], a1 = As[cur][k][tr + 1],
                  a2 = As[cur][k][tr + 2], a3 = As[cur][k][tr + 3];
            float b0 = Bs[cur][k][tc + 0], b1 = Bs[cur][k][tc + 1],
                  b2 = Bs[cur][k][tc + 2], b3 = Bs[cur][k][tc + 3];
            acc[0][0] += a0 * b0; acc[0][1] += a0 * b1; acc[0][2] += a0 * b2; acc[0][3] += a0 * b3;
            acc[1][0] += a1 * b0; acc[1][1] += a1 * b1; acc[1][2] += a1 * b2; acc[1][3] += a1 * b3;
            acc[2][0] += a2 * b0; acc[2][1] += a2 * b1; acc[2][2] += a2 * b2; acc[2][3] += a2 * b3;
            acc[3][0] += a3 * b0; acc[3][1] += a3 * b1; acc[3][2] += a3 * b2; acc[3][3] += a3 * b3;
        }
        __syncthreads();
    }

    #pragma unroll
    for (int j = 0; j < 4; j++) {
        float bj = bias[n0 + tc + j];
        #pragma unroll
        for (int i = 0; i < 4; i++) {
            int m = m0 + tr + i;
            if (m < NN)
                inputs[((size_t)b * NN + m) * 256 + half * 128 + n0 + tc + j] = acc[i][j] + bj;
        }
    }
}

// ---------------- fused GRU gates ----------------
__global__ void gates_kernel(const float* __restrict__ gi,
                             const float* __restrict__ gh,
                             const float* __restrict__ hidden,
                             float* __restrict__ out)
{
    int idx = blockIdx.x * blockDim.x + threadIdx.x;   // over MTOK * 32 float4
    if (idx >= MTOK * (DD / 4)) return;
    int m  = idx >> 5;
    int d  = (idx & 31) << 2;
    size_t gbase = (size_t)m * 384 + d;

    float4 ir = *reinterpret_cast<const float4*>(gi + gbase);
    float4 ii = *reinterpret_cast<const float4*>(gi + gbase + 128);
    float4 in_ = *reinterpret_cast<const float4*>(gi + gbase + 256);
    float4 hr = *reinterpret_cast<const float4*>(gh + gbase);
    float4 hi = *reinterpret_cast<const float4*>(gh + gbase + 128);
    float4 hn = *reinterpret_cast<const float4*>(gh + gbase + 256);
    float4 hd = reinterpret_cast<const float4*>(hidden)[idx];

    float4 o;
    {
        float r  = 1.f / (1.f + expf(-(ir.x + hr.x)));
        float ig = 1.f / (1.f + expf(-(ii.x + hi.x)));
        float no = tanhf(in_.x + r * hn.x);
        o.x = no + ig * (hd.x - no);
    }
    {
        float r  = 1.f / (1.f + expf(-(ir.y + hr.y)));
        float ig = 1.f / (1.f + expf(-(ii.y + hi.y)));
        float no = tanhf(in_.y + r * hn.y);
        o.y = no + ig * (hd.y - no);
    }
    {
        float r  = 1.f / (1.f + expf(-(ir.z + hr.z)));
        float ig = 1.f / (1.f + expf(-(ii.z + hi.z)));
        float no = tanhf(in_.z + r * hn.z);
        o.z = no + ig * (hd.z - no);
    }
    {
        float r  = 1.f / (1.f + expf(-(ir.w + hr.w)));
        float ig = 1.f / (1.f + expf(-(ii.w + hi.w)));
        float no = tanhf(in_.w + r * hn.w);
        o.w = no + ig * (hd.w - no);
    }
    reinterpret_cast<float4*>(out)[idx] = o;
}

// ---------------- launch ----------------
extern "C" void kernel_launch(void* const* d_in, const int* in_sizes, int n_in,
                              void* d_out, int out_size)
{
    // metadata order: x, A, emb, w_in, b_in, w_out, b_out, w_ih, b_ih, w_hh, b_hh, b_iah, b_oah
    const int*   x     = (const int*)  d_in[0];
    const float* A     = (const float*)d_in[1];
    const float* emb   = (const float*)d_in[2];
    const float* w_in  = (const float*)d_in[3];
    const float* b_in  = (const float*)d_in[4];
    const float* w_out = (const float*)d_in[5];
    const float* b_out = (const float*)d_in[6];
    const float* w_ih  = (const float*)d_in[7];
    const float* b_ih  = (const float*)d_in[8];
    const float* w_hh  = (const float*)d_in[9];
    const float* b_hh  = (const float*)d_in[10];
    const float* b_iah = (const float*)d_in[11];
    const float* b_oah = (const float*)d_in[12];
    float* out = (float*)d_out;

    float *hidden, *h2, *inputs, *gi, *gh, *w2, *bias2;
    cudaGetSymbolAddress((void**)&hidden, g_hidden);
    cudaGetSymbolAddress((void**)&h2,     g_h2);
    cudaGetSymbolAddress((void**)&inputs, g_inputs);
    cudaGetSymbolAddress((void**)&gi,     g_gi);
    cudaGetSymbolAddress((void**)&gh,     g_gh);
    cudaGetSymbolAddress((void**)&w2,     g_w2);
    cudaGetSymbolAddress((void**)&bias2,  g_bias2);

    // 0. pack [w_in ; w_out] -> w2, [b_in ; b_out] -> bias2
    pack_w2_kernel<<<(DD * DD + 255) / 256, 256>>>(w_in, b_in, w_out, b_out, w2, bias2);

    // 1. gather
    {
        int total = MTOK * (DD / 4);
        gather_kernel<<<(total + 255) / 256, 256>>>(x, emb, hidden);
    }

    // 2. h2 = hidden @ w2^T + bias2   (single GEMM, N=256)
    {
        dim3 grid(MTOK / BM, (2 * DD) / BN);
        gemm_tn_bias<<<grid, 256>>>(hidden, DD, w2, bias2, h2, 256, DD);
    }

    // 3. inputs = concat(A1 @ h_in + b_iah, A2 @ h_out + b_oah)
    {
        dim3 grid((NN + BM - 1) / BM, DD / BN, BB * 2);
        gemm_batched_adj<<<grid, 256>>>(A, h2, b_iah, b_oah, inputs);
    }

    // 4. gi = inputs @ w_ih^T + b_ih ; gh = hidden @ w_hh^T + b_hh
    {
        dim3 grid_gi(MTOK / BM, (3 * DD) / BN);
        gemm_tn_bias<<<grid_gi, 256>>>(inputs, 256, w_ih, b_ih, gi, 384, 256);
        gemm_tn_bias<<<grid_gi, 256>>>(hidden, DD,  w_hh, b_hh, gh, 384, DD);
    }

    // 5. fused gates -> out
    {
        int total = MTOK * (DD / 4);
        gates_kernel<<<(total + 255) / 256, 256>>>(gi, gh, hidden, out);
    }
}

// round 4
// speedup vs baseline: 2.0458x; 2.0458x over previous
#include <cuda_runtime.h>
#include <cuda_bf16.h>
#include <math.h>
#include <stdint.h>

// Problem constants
#define BB 512
#define NN 200
#define DD 128
#define MTOK (BB * NN)        // 102400 tokens

// ---------------- scratch (static device globals; no allocation) ----------------
__device__ float g_hidden[MTOK * DD];          // (102400, 128)
__device__ float g_h2    [MTOK * 2 * DD];      // (102400, 256)  [h_in | h_out]
__device__ float g_inputs[MTOK * 2 * DD];      // (102400, 256)
__device__ float g_gi    [MTOK * 3 * DD];      // (102400, 384)
__device__ float g_gh    [MTOK * 3 * DD];      // (102400, 384)
__device__ float g_w2    [2 * DD * DD];        // (256, 128)  [w_in ; w_out]
__device__ float g_bias2 [2 * DD];             // (256)

// ---------------- PTX helpers ----------------
__device__ __forceinline__ uint32_t cvta_s(const void* p) {
    return (uint32_t)__cvta_generic_to_shared(p);
}
__device__ __forceinline__ void ldsm4(uint32_t* r, uint32_t a) {
    asm volatile("ldmatrix.sync.aligned.m8n8.x4.shared.b16 {%0,%1,%2,%3}, [%4];\n"
        : "=r"(r[0]), "=r"(r[1]), "=r"(r[2]), "=r"(r[3]) : "r"(a));
}
__device__ __forceinline__ void ldsm2(uint32_t* r, uint32_t a) {
    asm volatile("ldmatrix.sync.aligned.m8n8.x2.shared.b16 {%0,%1}, [%2];\n"
        : "=r"(r[0]), "=r"(r[1]) : "r"(a));
}
__device__ __forceinline__ void ldsm2t(uint32_t* r, uint32_t a) {
    asm volatile("ldmatrix.sync.aligned.m8n8.x2.trans.shared.b16 {%0,%1}, [%2];\n"
        : "=r"(r[0]), "=r"(r[1]) : "r"(a));
}
__device__ __forceinline__ void mma16816(float* c, const uint32_t* a, const uint32_t* b) {
    asm volatile("mma.sync.aligned.m16n8k16.row.col.f32.bf16.bf16.f32 "
        "{%0,%1,%2,%3}, {%4,%5,%6,%7}, {%8,%9}, {%0,%1,%2,%3};\n"
        : "+f"(c[0]), "+f"(c[1]), "+f"(c[2]), "+f"(c[3])
        : "r"(a[0]), "r"(a[1]), "r"(a[2]), "r"(a[3]), "r"(b[0]), "r"(b[1]));
}
__device__ __forceinline__ uint32_t pk(float a, float b) {
    __nv_bfloat162 h = __floats2bfloat162_rn(a, b);
    return *reinterpret_cast<uint32_t*>(&h);
}
// split x into big(bf16) + small(bf16 of residual)
__device__ __forceinline__ void split2(float x, float y, uint32_t& bg, uint32_t& sm) {
    float bx = __bfloat162float(__float2bfloat16_rn(x));
    float by = __bfloat162float(__float2bfloat16_rn(y));
    bg = pk(bx, by);
    sm = pk(x - bx, y - by);
}
// 8 consecutive floats -> 16B big chunk + 16B small chunk
__device__ __forceinline__ void conv8(const float4& u, const float4& v, uint4& bg, uint4& sm) {
    split2(u.x, u.y, bg.x, sm.x);
    split2(u.z, u.w, bg.y, sm.y);
    split2(v.x, v.y, bg.z, sm.z);
    split2(v.z, v.w, bg.w, sm.w);
}

// ---------------- pack w_in/w_out ----------------
__global__ void pack_w2_kernel(const float* __restrict__ w_in,
                               const float* __restrict__ b_in,
                               const float* __restrict__ w_out,
                               const float* __restrict__ b_out,
                               float* __restrict__ w2,
                               float* __restrict__ bias2)
{
    int i = blockIdx.x * blockDim.x + threadIdx.x;
    if (i < DD * DD) {
        w2[i] = w_in[i];
        w2[DD * DD + i] = w_out[i];
    }
    if (i < DD) {
        bias2[i] = b_in[i];
        bias2[DD + i] = b_out[i];
    }
}

// ---------------- gather ----------------
__global__ void gather_kernel(const int* __restrict__ x,
                              const float* __restrict__ emb,
                              float* __restrict__ hidden)
{
    int idx = blockIdx.x * blockDim.x + threadIdx.x;
    if (idx >= MTOK * (DD / 4)) return;
    int m  = idx >> 5;
    int k4 = idx & 31;
    int t  = x[m];
    reinterpret_cast<float4*>(hidden)[idx] =
        reinterpret_cast<const float4*>(emb + (size_t)t * DD)[k4];
}

// ============================================================================
// TN GEMM on tensor cores, split-bf16 (3-mma) for fp32-class accuracy.
// C[m,n] = A[m,:K] . W[n,:K] + bias[n]
// Block 128 thr (4 warps), tile 128x64, warp tile 64x32 (warp grid 2m x 2n).
// Requires M%128==0, N%64==0, K%32==0 (all call sites satisfy).
// smem rows padded to 80B -> ldmatrix conflict-free without XOR swizzle.
// ============================================================================
#define TN_ABIG 0
#define TN_ASM  10240          // 128 rows * 80B
#define TN_BBIG 20480
#define TN_BSM  25600          // 64 rows * 80B
#define TN_BUF  30720
#define TN_SMEM (2 * TN_BUF)   // 61440

__global__ void __launch_bounds__(128) gemm_tn_mma(
    const float* __restrict__ A, int lda,
    const float* __restrict__ W,
    const float* __restrict__ bias,
    float* __restrict__ C, int ldc, int K)
{
    extern __shared__ char sm_[];
    const int tid  = threadIdx.x;
    const int lane = tid & 31;
    const int warp = tid >> 5;
    const int wm = warp & 1;          // 0,1 -> m offset *64
    const int wn = warp >> 1;         // 0,1 -> n offset *32
    const size_t m0 = (size_t)blockIdx.x * 128;
    const int    n0 = blockIdx.y * 64;

    float acc[4][4][4];
    #pragma unroll
    for (int i = 0; i < 4; i++)
        #pragma unroll
        for (int j = 0; j < 4; j++)
            #pragma unroll
            for (int q = 0; q < 4; q++) acc[i][j][q] = 0.f;

    const int ntiles = K >> 5;

    const float* Ag = A + (m0 + tid) * (size_t)lda;
    const int brow = tid >> 1;
    const int bc0  = (tid & 1) * 2;
    const float* Wg = W + (size_t)(n0 + brow) * K;

    float4 stA[8];
    float4 stB[4];

    const int a_r = lane & 15, a_c = lane >> 4;
    const int b_r = lane & 7,  b_c = (lane >> 3) & 1;

    // ---- prologue: tile 0 ----
    #pragma unroll
    for (int c = 0; c < 4; c++) {
        stA[2 * c]     = *reinterpret_cast<const float4*>(Ag + c * 8);
        stA[2 * c + 1] = *reinterpret_cast<const float4*>(Ag + c * 8 + 4);
    }
    #pragma unroll
    for (int i = 0; i < 2; i++) {
        int c = bc0 + i;
        stB[2 * i]     = *reinterpret_cast<const float4*>(Wg + c * 8);
        stB[2 * i + 1] = *reinterpret_cast<const float4*>(Wg + c * 8 + 4);
    }
    {
        char* base = sm_;
        #pragma unroll
        for (int c = 0; c < 4; c++) {
            uint4 bg, sv; conv8(stA[2 * c], stA[2 * c + 1], bg, sv);
            *reinterpret_cast<uint4*>(base + TN_ABIG + tid * 80 + c * 16) = bg;
            *reinterpret_cast<uint4*>(base + TN_ASM  + tid * 80 + c * 16) = sv;
        }
        #pragma unroll
        for (int i = 0; i < 2; i++) {
            int c = bc0 + i;
            uint4 bg, sv; conv8(stB[2 * i], stB[2 * i + 1], bg, sv);
            *reinterpret_cast<uint4*>(base + TN_BBIG + brow * 80 + c * 16) = bg;
            *reinterpret_cast<uint4*>(base + TN_BSM  + brow * 80 + c * 16) = sv;
        }
    }
    __syncthreads();

    for (int t = 0; t < ntiles; t++) {
        if (t + 1 < ntiles) {
            int k0 = (t + 1) * 32;
            #pragma unroll
            for (int c = 0; c < 4; c++) {
                stA[2 * c]     = *reinterpret_cast<const float4*>(Ag + k0 + c * 8);
                stA[2 * c + 1] = *reinterpret_cast<const float4*>(Ag + k0 + c * 8 + 4);
            }
            #pragma unroll
            for (int i = 0; i < 2; i++) {
                int c = bc0 + i;
                stB[2 * i]     = *reinterpret_cast<const float4*>(Wg + k0 + c * 8);
                stB[2 * i + 1] = *reinterpret_cast<const float4*>(Wg + k0 + c * 8 + 4);
            }
        }

        {
            const int buf = t & 1;
            uint32_t aAb = cvta_s(sm_ + buf * TN_BUF + TN_ABIG) + (wm * 64 + a_r) * 80 + a_c * 16;
            uint32_t aAs = aAb + (TN_ASM - TN_ABIG);
            uint32_t aBb = cvta_s(sm_ + buf * TN_BUF + TN_BBIG) + (wn * 32 + b_r) * 80 + b_c * 16;
            uint32_t aBs = aBb + (TN_BSM - TN_BBIG);
            #pragma unroll
            for (int ks = 0; ks < 2; ks++) {
                uint32_t fa[4][4], fas[4][4], fb[4][2], fbs[4][2];
                #pragma unroll
                for (int mi = 0; mi < 4; mi++) {
                    ldsm4(fa[mi],  aAb + mi * (16 * 80) + ks * 32);
                    ldsm4(fas[mi], aAs + mi * (16 * 80) + ks * 32);
                }
                #pragma unroll
                for (int nj = 0; nj < 4; nj++) {
                    ldsm2(fb[nj],  aBb + nj * (8 * 80) + ks * 32);
                    ldsm2(fbs[nj], aBs + nj * (8 * 80) + ks * 32);
                }
                #pragma unroll
                for (int mi = 0; mi < 4; mi++)
                    #pragma unroll
                    for (int nj = 0; nj < 4; nj++) {
                        mma16816(acc[mi][nj], fa[mi],  fb[nj]);
                        mma16816(acc[mi][nj], fa[mi],  fbs[nj]);
                        mma16816(acc[mi][nj], fas[mi], fb[nj]);
                    }
            }
        }

        if (t + 1 < ntiles) {
            char* base = sm_ + ((t + 1) & 1) * TN_BUF;
            #pragma unroll
            for (int c = 0; c < 4; c++) {
                uint4 bg, sv; conv8(stA[2 * c], stA[2 * c + 1], bg, sv);
                *reinterpret_cast<uint4*>(base + TN_ABIG + tid * 80 + c * 16) = bg;
                *reinterpret_cast<uint4*>(base + TN_ASM  + tid * 80 + c * 16) = sv;
            }
            #pragma unroll
            for (int i = 0; i < 2; i++) {
                int c = bc0 + i;
                uint4 bg, sv; conv8(stB[2 * i], stB[2 * i + 1], bg, sv);
                *reinterpret_cast<uint4*>(base + TN_BBIG + brow * 80 + c * 16) = bg;
                *reinterpret_cast<uint4*>(base + TN_BSM  + brow * 80 + c * 16) = sv;
            }
        }
        __syncthreads();
    }

    // epilogue: bias + store
    const int r0  = lane >> 2;
    const int c0l = (lane & 3) * 2;
    #pragma unroll
    for (int mi = 0; mi < 4; mi++) {
        #pragma unroll
        for (int nj = 0; nj < 4; nj++) {
            int col = n0 + wn * 32 + nj * 8 + c0l;
            float2 bz = *reinterpret_cast<const float2*>(bias + col);
            size_t row1 = m0 + wm * 64 + mi * 16 + r0;
            float2 v0 = make_float2(acc[mi][nj][0] + bz.x, acc[mi][nj][1] + bz.y);
            float2 v1 = make_float2(acc[mi][nj][2] + bz.x, acc[mi][nj][3] + bz.y);
            *reinterpret_cast<float2*>(C + row1 * (size_t)ldc + col) = v0;
            *reinterpret_cast<float2*>(C + (row1 + 8) * (size_t)ldc + col) = v1;
        }
    }
}

// ============================================================================
// Batched adjacency GEMM on tensor cores (B tile stored [k][n], consumed via
// ldmatrix.trans). Per (b, half): C(200x128) = A(200x200) @ H(200x128).
// grid = (2 mtiles, 2 ntiles, 1024 = b*2+half)
// ============================================================================
#define ADJ_ABIG 0
#define ADJ_ASM  10240
#define ADJ_BBIG 20480         // 32 rows * 128B = 4096
#define ADJ_BSM  24576
#define ADJ_BUF  28672
#define ADJ_SMEM (2 * ADJ_BUF) // 57344

__global__ void __launch_bounds__(128) gemm_adj_mma(
    const float* __restrict__ Aten,    // (512, 200, 400)
    const float* __restrict__ h2,      // (102400, 256)
    const float* __restrict__ b_iah,
    const float* __restrict__ b_oah,
    float* __restrict__ inputs)        // (102400, 256)
{
    extern __shared__ char sm_[];
    const int tid  = threadIdx.x;
    const int lane = tid & 31;
    const int warp = tid >> 5;
    const int wm = warp & 1;
    const int wn = warp >> 1;
    const int half = blockIdx.z & 1;
    const int b    = blockIdx.z >> 1;
    const int m0   = blockIdx.x * 128;   // 0, 128
    const int n0   = blockIdx.y * 64;    // 0, 64

    const float* Ab   = Aten + (size_t)b * NN * (2 * NN) + half * NN;
    const float* Hb   = h2   + (size_t)b * NN * 256 + half * 128;
    const float* bias = half ? b_oah : b_iah;

    float acc[4][4][4];
    #pragma unroll
    for (int i = 0; i < 4; i++)
        #pragma unroll
        for (int j = 0; j < 4; j++)
            #pragma unroll
            for (int q = 0; q < 4; q++) acc[i][j][q] = 0.f;

    const int ntiles = 7;                 // ceil(200/32)

    const bool  rvalid = (m0 + tid) < NN;
    const float* Ag = Ab + (size_t)(m0 + tid) * (2 * NN);
    const int bkr = tid >> 2;             // 0..31 (k row)
    const int bc0 = (tid & 3) * 2;        // n-chunk pair base (of 8)
    const float* Hg = Hb + (size_t)bkr * 256 + n0;

    float4 stA[8];
    float4 stB[4];
    const float4 z4 = make_float4(0.f, 0.f, 0.f, 0.f);

    const int a_r = lane & 15, a_c = lane >> 4;
    const int b_rk = lane & 15;

    // ---- prologue: tile 0 (k0 = 0) ----
    #pragma unroll
    for (int c = 0; c < 4; c++) {
        bool kv = rvalid && (c * 8 < NN);
        stA[2 * c]     = kv ? *reinterpret_cast<const float4*>(Ag + c * 8)     : z4;
        stA[2 * c + 1] = kv ? *reinterpret_cast<const float4*>(Ag + c * 8 + 4) : z4;
    }
    {
        bool bv = bkr < NN;
        #pragma unroll
        for (int i = 0; i < 2; i++) {
            int c = bc0 + i;
            stB[2 * i]     = bv ? *reinterpret_cast<const float4*>(Hg + c * 8)     : z4;
            stB[2 * i + 1] = bv ? *reinterpret_cast<const float4*>(Hg + c * 8 + 4) : z4;
        }
    }
    {
        char* base = sm_;
        #pragma unroll
        for (int c = 0; c < 4; c++) {
            uint4 bg, sv; conv8(stA[2 * c], stA[2 * c + 1], bg, sv);
            *reinterpret_cast<uint4*>(base + ADJ_ABIG + tid * 80 + c * 16) = bg;
            *reinterpret_cast<uint4*>(base + ADJ_ASM  + tid * 80 + c * 16) = sv;
        }
        #pragma unroll
        for (int i = 0; i < 2; i++) {
            int c = bc0 + i;
            uint32_t off = bkr * 128 + ((c * 16) ^ ((bkr & 7) << 4));
            uint4 bg, sv; conv8(stB[2 * i], stB[2 * i + 1], bg, sv);
            *reinterpret_cast<uint4*>(base + ADJ_BBIG + off) = bg;
            *reinterpret_cast<uint4*>(base + ADJ_BSM  + off) = sv;
        }
    }
    __syncthreads();

    for (int t = 0; t < ntiles; t++) {
        if (t + 1 < ntiles) {
            int k0 = (t + 1) * 32;
            #pragma unroll
            for (int c = 0; c < 4; c++) {
                bool kv = rvalid && (k0 + c * 8 < NN);
                stA[2 * c]     = kv ? *reinterpret_cast<const float4*>(Ag + k0 + c * 8)     : z4;
                stA[2 * c + 1] = kv ? *reinterpret_cast<const float4*>(Ag + k0 + c * 8 + 4) : z4;
            }
            bool bv = (k0 + bkr) < NN;
            #pragma unroll
            for (int i = 0; i < 2; i++) {
                int c = bc0 + i;
                stB[2 * i]     = bv ? *reinterpret_cast<const float4*>(Hg + (size_t)k0 * 256 + c * 8)     : z4;
                stB[2 * i + 1] = bv ? *reinterpret_cast<const float4*>(Hg + (size_t)k0 * 256 + c * 8 + 4) : z4;
            }
        }

        {
            const int buf = t & 1;
            uint32_t aAb = cvta_s(sm_ + buf * ADJ_BUF + ADJ_ABIG) + (wm * 64 + a_r) * 80 + a_c * 16;
            uint32_t aAs = aAb + (ADJ_ASM - ADJ_ABIG);
            uint32_t aBbase = cvta_s(sm_ + buf * ADJ_BUF + ADJ_BBIG);
            #pragma unroll
            for (int ks = 0; ks < 2; ks++) {
                uint32_t fa[4][4], fas[4][4], fb[4][2], fbs[4][2];
                #pragma unroll
                for (int mi = 0; mi < 4; mi++) {
                    ldsm4(fa[mi],  aAb + mi * (16 * 80) + ks * 32);
                    ldsm4(fas[mi], aAs + mi * (16 * 80) + ks * 32);
                }
                #pragma unroll
                for (int nj = 0; nj < 4; nj++) {
                    int cn = wn * 4 + nj;
                    uint32_t addr = aBbase + (ks * 16 + b_rk) * 128
                                  + ((cn * 16) ^ ((b_rk & 7) << 4));
                    ldsm2t(fb[nj],  addr);
                    ldsm2t(fbs[nj], addr + (ADJ_BSM - ADJ_BBIG));
                }
                #pragma unroll
                for (int mi = 0; mi < 4; mi++)
                    #pragma unroll
                    for (int nj = 0; nj < 4; nj++) {
                        mma16816(acc[mi][nj], fa[mi],  fb[nj]);
                        mma16816(acc[mi][nj], fa[mi],  fbs[nj]);
                        mma16816(acc[mi][nj], fas[mi], fb[nj]);
                    }
            }
        }

        if (t + 1 < ntiles) {
            char* base = sm_ + ((t + 1) & 1) * ADJ_BUF;
            #pragma unroll
            for (int c = 0; c < 4; c++) {
                uint4 bg, sv; conv8(stA[2 * c], stA[2 * c + 1], bg, sv);
                *reinterpret_cast<uint4*>(base + ADJ_ABIG + tid * 80 + c * 16) = bg;
                *reinterpret_cast<uint4*>(base + ADJ_ASM  + tid * 80 + c * 16) = sv;
            }
            #pragma unroll
            for (int i = 0; i < 2; i++) {
                int c = bc0 + i;
                uint32_t off = bkr * 128 + ((c * 16) ^ ((bkr & 7) << 4));
                uint4 bg, sv; conv8(stB[2 * i], stB[2 * i + 1], bg, sv);
                *reinterpret_cast<uint4*>(base + ADJ_BBIG + off) = bg;
                *reinterpret_cast<uint4*>(base + ADJ_BSM  + off) = sv;
            }
        }
        __syncthreads();
    }

    // epilogue
    const int r0  = lane >> 2;
    const int c0l = (lane & 3) * 2;
    #pragma unroll
    for (int mi = 0; mi < 4; mi++) {
        #pragma unroll
        for (int nj = 0; nj < 4; nj++) {
            int col = n0 + wn * 32 + nj * 8 + c0l;
            float2 bz = *reinterpret_cast<const float2*>(bias + col);
            int row1 = m0 + wm * 64 + mi * 16 + r0;
            if (row1 < NN) {
                float2 v0 = make_float2(acc[mi][nj][0] + bz.x, acc[mi][nj][1] + bz.y);
                *reinterpret_cast<float2*>(inputs + ((size_t)b * NN + row1) * 256 + half * 128 + col) = v0;
            }
            if (row1 + 8 < NN) {
                float2 v1 = make_float2(acc[mi][nj][2] + bz.x, acc[mi][nj][3] + bz.y);
                *reinterpret_cast<float2*>(inputs + ((size_t)b * NN + row1 + 8) * 256 + half * 128 + col) = v1;
            }
        }
    }
}

// ---------------- fused GRU gates ----------------
__global__ void gates_kernel(const float* __restrict__ gi,
                             const float* __restrict__ gh,
                             const float* __restrict__ hidden,
                             float* __restrict__ out)
{
    int idx = blockIdx.x * blockDim.x + threadIdx.x;
    if (idx >= MTOK * (DD / 4)) return;
    int m = idx >> 5;
    int d = (idx & 31) << 2;
    size_t gbase = (size_t)m * 384 + d;

    float4 ir  = *reinterpret_cast<const float4*>(gi + gbase);
    float4 ii  = *reinterpret_cast<const float4*>(gi + gbase + 128);
    float4 in_ = *reinterpret_cast<const float4*>(gi + gbase + 256);
    float4 hr  = *reinterpret_cast<const float4*>(gh + gbase);
    float4 hi  = *reinterpret_cast<const float4*>(gh + gbase + 128);
    float4 hn  = *reinterpret_cast<const float4*>(gh + gbase + 256);
    float4 hd  = reinterpret_cast<const float4*>(hidden)[idx];

    float4 o;
    {
        float r  = 1.f / (1.f + expf(-(ir.x + hr.x)));
        float ig = 1.f / (1.f + expf(-(ii.x + hi.x)));
        float no = tanhf(in_.x + r * hn.x);
        o.x = no + ig * (hd.x - no);
    }
    {
        float r  = 1.f / (1.f + expf(-(ir.y + hr.y)));
        float ig = 1.f / (1.f + expf(-(ii.y + hi.y)));
        float no = tanhf(in_.y + r * hn.y);
        o.y = no + ig * (hd.y - no);
    }
    {
        float r  = 1.f / (1.f + expf(-(ir.z + hr.z)));
        float ig = 1.f / (1.f + expf(-(ii.z + hi.z)));
        float no = tanhf(in_.z + r * hn.z);
        o.z = no + ig * (hd.z - no);
    }
    {
        float r  = 1.f / (1.f + expf(-(ir.w + hr.w)));
        float ig = 1.f / (1.f + expf(-(ii.w + hi.w)));
        float no = tanhf(in_.w + r * hn.w);
        o.w = no + ig * (hd.w - no);
    }
    reinterpret_cast<float4*>(out)[idx] = o;
}

// ---------------- launch ----------------
extern "C" void kernel_launch(void* const* d_in, const int* in_sizes, int n_in,
                              void* d_out, int out_size)
{
    const int*   x     = (const int*)  d_in[0];
    const float* A     = (const float*)d_in[1];
    const float* emb   = (const float*)d_in[2];
    const float* w_in  = (const float*)d_in[3];
    const float* b_in  = (const float*)d_in[4];
    const float* w_out = (const float*)d_in[5];
    const float* b_out = (const float*)d_in[6];
    const float* w_ih  = (const float*)d_in[7];
    const float* b_ih  = (const float*)d_in[8];
    const float* w_hh  = (const float*)d_in[9];
    const float* b_hh  = (const float*)d_in[10];
    const float* b_iah = (const float*)d_in[11];
    const float* b_oah = (const float*)d_in[12];
    float* out = (float*)d_out;

    float *hidden, *h2, *inputs, *gi, *gh, *w2, *bias2;
    cudaGetSymbolAddress((void**)&hidden, g_hidden);
    cudaGetSymbolAddress((void**)&h2,     g_h2);
    cudaGetSymbolAddress((void**)&inputs, g_inputs);
    cudaGetSymbolAddress((void**)&gi,     g_gi);
    cudaGetSymbolAddress((void**)&gh,     g_gh);
    cudaGetSymbolAddress((void**)&w2,     g_w2);
    cudaGetSymbolAddress((void**)&bias2,  g_bias2);

    cudaFuncSetAttribute(gemm_tn_mma,  cudaFuncAttributeMaxDynamicSharedMemorySize, TN_SMEM);
    cudaFuncSetAttribute(gemm_adj_mma, cudaFuncAttributeMaxDynamicSharedMemorySize, ADJ_SMEM);

    // 0. pack weights
    pack_w2_kernel<<<(DD * DD + 255) / 256, 256>>>(w_in, b_in, w_out, b_out, w2, bias2);

    // 1. gather
    {
        int total = MTOK * (DD / 4);
        gather_kernel<<<(total + 255) / 256, 256>>>(x, emb, hidden);
    }

    // 2. h2 = hidden @ w2^T + bias2   (M=102400, N=256, K=128)
    gemm_tn_mma<<<dim3(MTOK / 128, 4), 128, TN_SMEM>>>(hidden, DD, w2, bias2, h2, 256, DD);

    // 3. inputs = concat(A1 @ h_in + b_iah, A2 @ h_out + b_oah)
    gemm_adj_mma<<<dim3(2, 2, BB * 2), 128, ADJ_SMEM>>>(A, h2, b_iah, b_oah, inputs);

    // 4. gi = inputs @ w_ih^T + b_ih (K=256); gh = hidden @ w_hh^T + b_hh (K=128)
    gemm_tn_mma<<<dim3(MTOK / 128, 6), 128, TN_SMEM>>>(inputs, 256, w_ih, b_ih, gi, 384, 256);
    gemm_tn_mma<<<dim3(MTOK / 128, 6), 128, TN_SMEM>>>(hidden, DD,  w_hh, b_hh, gh, 384, DD);

    // 5. gates
    {
        int total = MTOK * (DD / 4);
        gates_kernel<<<(total + 255) / 256, 256>>>(gi, gh, hidden, out);
    }
}